// round 1
// baseline (speedup 1.0000x reference)
#include <cuda_runtime.h>
#include <math_constants.h>

// TropicalLinear: out[n,o] = max_k( x[n,k] + w[o,k] ) + bias[o]
// N=128, IN=1024, OUT=1024, fp32.
// (reference's "soft - stop_gradient(soft)" is identically 0 in the forward pass)

#define BN 32          // N-tile per CTA
#define BO 32          // OUT-tile per CTA
#define KC 128         // K-chunk staged through smem
#define PADF 4         // 16B row pad to skew smem banks (keeps float4 alignment)
#define NTHREADS 256

#define N_TOT 128
#define IN_TOT 1024
#define OUT_TOT 1024

__global__ __launch_bounds__(NTHREADS, 1)
void tropical_linear_kernel(const float* __restrict__ x,     // [N, IN]
                            const float* __restrict__ w,     // [OUT, IN]
                            const float* __restrict__ bias,  // [OUT]
                            float* __restrict__ out)         // [N, OUT]
{
    __shared__ float xs[BN][KC + PADF];
    __shared__ float ws[BO][KC + PADF];

    const int t = threadIdx.x;
    const int o_base = blockIdx.x * BO;
    const int n_base = blockIdx.y * BN;

    // 16 x 16 thread grid; each thread owns a 2(n) x 2(o) micro-tile
    const int tx = t & 15;        // o-pair index
    const int ty = t >> 4;        // n-pair index
    const int o0 = tx * 2;
    const int n0 = ty * 2;

    float acc00 = -CUDART_INF_F, acc01 = -CUDART_INF_F;
    float acc10 = -CUDART_INF_F, acc11 = -CUDART_INF_F;

    for (int kc = 0; kc < IN_TOT; kc += KC) {
        // Stage tiles: 32 rows x 128 cols each = 1024 float4 per tile,
        // 256 threads -> 4 float4 per thread per tile. Fully coalesced
        // (warp covers 512B contiguous).
        #pragma unroll
        for (int r = 0; r < 4; r++) {
            int idx  = t + r * NTHREADS;   // 0..1023
            int row  = idx >> 5;           // 32 float4 per row
            int col4 = idx & 31;
            float4 xv = *reinterpret_cast<const float4*>(
                &x[(n_base + row) * IN_TOT + kc + col4 * 4]);
            *reinterpret_cast<float4*>(&xs[row][col4 * 4]) = xv;
            float4 wv = *reinterpret_cast<const float4*>(
                &w[(o_base + row) * IN_TOT + kc + col4 * 4]);
            *reinterpret_cast<float4*>(&ws[row][col4 * 4]) = wv;
        }
        __syncthreads();

        // Mainloop: 4 LDS.128 feed 32 (FADD + FMNMX) lane-ops.
        #pragma unroll
        for (int k4 = 0; k4 < KC / 4; k4++) {
            float4 xa = *reinterpret_cast<const float4*>(&xs[n0    ][k4 * 4]);
            float4 xb = *reinterpret_cast<const float4*>(&xs[n0 + 1][k4 * 4]);
            float4 wa = *reinterpret_cast<const float4*>(&ws[o0    ][k4 * 4]);
            float4 wb = *reinterpret_cast<const float4*>(&ws[o0 + 1][k4 * 4]);

            // 2x2 micro-tile, 4 k-steps each. Independent accumulator chains
            // give the scheduler ILP across the fmax latency (4 cyc).
            acc00 = fmaxf(acc00, xa.x + wa.x);
            acc01 = fmaxf(acc01, xa.x + wb.x);
            acc10 = fmaxf(acc10, xb.x + wa.x);
            acc11 = fmaxf(acc11, xb.x + wb.x);

            acc00 = fmaxf(acc00, xa.y + wa.y);
            acc01 = fmaxf(acc01, xa.y + wb.y);
            acc10 = fmaxf(acc10, xb.y + wa.y);
            acc11 = fmaxf(acc11, xb.y + wb.y);

            acc00 = fmaxf(acc00, xa.z + wa.z);
            acc01 = fmaxf(acc01, xa.z + wb.z);
            acc10 = fmaxf(acc10, xb.z + wa.z);
            acc11 = fmaxf(acc11, xb.z + wb.z);

            acc00 = fmaxf(acc00, xa.w + wa.w);
            acc01 = fmaxf(acc01, xa.w + wb.w);
            acc10 = fmaxf(acc10, xb.w + wa.w);
            acc11 = fmaxf(acc11, xb.w + wb.w);
        }
        __syncthreads();
    }

    const float b0 = bias[o_base + o0];
    const float b1 = bias[o_base + o0 + 1];
    out[(n_base + n0    ) * OUT_TOT + o_base + o0    ] = acc00 + b0;
    out[(n_base + n0    ) * OUT_TOT + o_base + o0 + 1] = acc01 + b1;
    out[(n_base + n0 + 1) * OUT_TOT + o_base + o0    ] = acc10 + b0;
    out[(n_base + n0 + 1) * OUT_TOT + o_base + o0 + 1] = acc11 + b1;
}

extern "C" void kernel_launch(void* const* d_in, const int* in_sizes, int n_in,
                              void* d_out, int out_size) {
    const float* x    = (const float*)d_in[0];   // [128, 1024]
    const float* w    = (const float*)d_in[1];   // [1024, 1024]
    const float* bias = (const float*)d_in[2];   // [1024]
    float* out        = (float*)d_out;           // [128, 1024]

    dim3 grid(OUT_TOT / BO, N_TOT / BN);         // 32 x 4 = 128 CTAs
    tropical_linear_kernel<<<grid, NTHREADS>>>(x, w, bias, out);
}

// round 2
// speedup vs baseline: 1.2667x; 1.2667x over previous
#include <cuda_runtime.h>
#include <math_constants.h>

// TropicalLinear: out[n,o] = max_k( x[n,k] + w[o,k] ) + bias[o]
// N=128, IN=1024, OUT=1024, fp32.
// forward of reference: soft - stop_gradient(soft) == 0, so exact max-plus matmul.
//
// v2: split-K=4 for occupancy (512 CTAs), conflict-free mainloop LDS
//     ((tx, tx+16) row split -> 33x16B odd stride), two-kernel reduce.

#define BN 32
#define BO 32
#define KC 128
#define ROWF (KC + 4)      // 132 floats: per-thread o-stride 132*4B = 33*16B (odd phase) -> conflict-free LDS.128
#define NTHREADS 256
#define KSPLIT 4

#define N_TOT 128
#define IN_TOT 1024
#define OUT_TOT 1024
#define KPER (IN_TOT / KSPLIT)   // 256

// split-K partial maxima: [KSPLIT][N][OUT]
__device__ float g_partial[KSPLIT * N_TOT * OUT_TOT];

__global__ __launch_bounds__(NTHREADS, 3)
void tropical_partial_kernel(const float* __restrict__ x,   // [N, IN]
                             const float* __restrict__ w)   // [OUT, IN]
{
    __shared__ float xs[BN][ROWF];
    __shared__ float ws[BO][ROWF];

    const int t = threadIdx.x;
    const int o_base = blockIdx.x * BO;
    const int n_base = blockIdx.y * BN;
    const int kz     = blockIdx.z;
    const int kc0    = kz * KPER;

    const int tx = t & 15;
    const int ty = t >> 4;
    // micro-tile rows split by +16 => LDS stride between consecutive tx is
    // ROWF floats = 528B = 33 x 16B (odd) -> bank-conflict-free LDS.128
    const int nA = ty, nB = ty + 16;
    const int oA = tx, oB = tx + 16;

    float acc00 = -CUDART_INF_F, acc01 = -CUDART_INF_F;
    float acc10 = -CUDART_INF_F, acc11 = -CUDART_INF_F;

    for (int c = 0; c < KPER; c += KC) {
        const int kc = kc0 + c;
        // stage: 32 rows x 128 cols per tile = 1024 float4 / tile,
        // 256 threads -> 4 float4/thread/tile, coalesced LDG.128 + STS.128
        #pragma unroll
        for (int r = 0; r < 4; r++) {
            int idx  = t + r * NTHREADS;
            int row  = idx >> 5;
            int col4 = idx & 31;
            float4 xv = *reinterpret_cast<const float4*>(
                &x[(n_base + row) * IN_TOT + kc + col4 * 4]);
            *reinterpret_cast<float4*>(&xs[row][col4 * 4]) = xv;
            float4 wv = *reinterpret_cast<const float4*>(
                &w[(o_base + row) * IN_TOT + kc + col4 * 4]);
            *reinterpret_cast<float4*>(&ws[row][col4 * 4]) = wv;
        }
        __syncthreads();

        #pragma unroll 8
        for (int k4 = 0; k4 < KC / 4; k4++) {
            float4 xa = *reinterpret_cast<const float4*>(&xs[nA][k4 * 4]);
            float4 xb = *reinterpret_cast<const float4*>(&xs[nB][k4 * 4]);
            float4 wa = *reinterpret_cast<const float4*>(&ws[oA][k4 * 4]);
            float4 wb = *reinterpret_cast<const float4*>(&ws[oB][k4 * 4]);

            acc00 = fmaxf(acc00, xa.x + wa.x);
            acc01 = fmaxf(acc01, xa.x + wb.x);
            acc10 = fmaxf(acc10, xb.x + wa.x);
            acc11 = fmaxf(acc11, xb.x + wb.x);

            acc00 = fmaxf(acc00, xa.y + wa.y);
            acc01 = fmaxf(acc01, xa.y + wb.y);
            acc10 = fmaxf(acc10, xb.y + wa.y);
            acc11 = fmaxf(acc11, xb.y + wb.y);

            acc00 = fmaxf(acc00, xa.z + wa.z);
            acc01 = fmaxf(acc01, xa.z + wb.z);
            acc10 = fmaxf(acc10, xb.z + wa.z);
            acc11 = fmaxf(acc11, xb.z + wb.z);

            acc00 = fmaxf(acc00, xa.w + wa.w);
            acc01 = fmaxf(acc01, xa.w + wb.w);
            acc10 = fmaxf(acc10, xb.w + wa.w);
            acc11 = fmaxf(acc11, xb.w + wb.w);
        }
        __syncthreads();
    }

    float* p = g_partial + kz * (N_TOT * OUT_TOT);
    p[(n_base + nA) * OUT_TOT + o_base + oA] = acc00;
    p[(n_base + nA) * OUT_TOT + o_base + oB] = acc01;
    p[(n_base + nB) * OUT_TOT + o_base + oA] = acc10;
    p[(n_base + nB) * OUT_TOT + o_base + oB] = acc11;
}

// max over KSPLIT partials + bias. One float4 of outputs per thread.
__global__ __launch_bounds__(256)
void tropical_reduce_kernel(const float* __restrict__ bias,
                            float* __restrict__ out)
{
    int i4 = blockIdx.x * blockDim.x + threadIdx.x;   // 0 .. 32767
    int base = i4 * 4;                                 // flat [n*OUT + o]
    int o = base & (OUT_TOT - 1);

    float4 m = *reinterpret_cast<const float4*>(&g_partial[base]);
    #pragma unroll
    for (int kz = 1; kz < KSPLIT; kz++) {
        float4 v = *reinterpret_cast<const float4*>(
            &g_partial[kz * (N_TOT * OUT_TOT) + base]);
        m.x = fmaxf(m.x, v.x);
        m.y = fmaxf(m.y, v.y);
        m.z = fmaxf(m.z, v.z);
        m.w = fmaxf(m.w, v.w);
    }
    float4 b = *reinterpret_cast<const float4*>(&bias[o]);
    m.x += b.x; m.y += b.y; m.z += b.z; m.w += b.w;
    *reinterpret_cast<float4*>(&out[base]) = m;
}

extern "C" void kernel_launch(void* const* d_in, const int* in_sizes, int n_in,
                              void* d_out, int out_size) {
    const float* x    = (const float*)d_in[0];   // [128, 1024]
    const float* w    = (const float*)d_in[1];   // [1024, 1024]
    const float* bias = (const float*)d_in[2];   // [1024]
    float* out        = (float*)d_out;           // [128, 1024]

    dim3 grid1(OUT_TOT / BO, N_TOT / BN, KSPLIT);   // 32 x 4 x 4 = 512 CTAs
    tropical_partial_kernel<<<grid1, NTHREADS>>>(x, w);

    int total4 = N_TOT * OUT_TOT / 4;               // 32768
    tropical_reduce_kernel<<<total4 / 256, 256>>>(bias, out);
}

// round 3
// speedup vs baseline: 1.5431x; 1.2183x over previous
#include <cuda_runtime.h>
#include <math_constants.h>

// TropicalLinear: out[n,o] = max_k( x[n,k] + w[o,k] ) + bias[o]
// N=128, IN=1024, OUT=1024, fp32.
// (forward of reference: soft - stop_gradient(soft) == 0 -> exact max-plus matmul)
//
// v3: 4x4 micro-tile (smem-crossbar balanced: 30B per issued instr),
//     split-K=8 single-chunk CTAs (512 CTAs, one wave), fused reduction via
//     last-CTA-per-tile atomic ticket (single kernel launch).

#define BN 32
#define BO 64
#define KC 128
#define ROWF (KC + 4)          // 132 floats: odd 16B-granule phase -> conflict-free LDS.128
#define NTHREADS 128
#define KSPLIT 8

#define N_TOT 128
#define IN_TOT 1024
#define OUT_TOT 1024

#define TILES_O (OUT_TOT / BO)   // 16
#define TILES_N (N_TOT / BN)     // 4

__device__ float g_partial[KSPLIT * N_TOT * OUT_TOT];   // [kz][n][o]
__device__ int   g_ticket[TILES_N * TILES_O];           // zero-init; self-resetting

__global__ __launch_bounds__(NTHREADS, 4)
void tropical_kernel(const float* __restrict__ x,     // [N, IN]
                     const float* __restrict__ w,     // [OUT, IN]
                     const float* __restrict__ bias,  // [OUT]
                     float* __restrict__ out)         // [N, OUT]
{
    __shared__ float xs[BN][ROWF];
    __shared__ float ws[BO][ROWF];
    __shared__ int   s_last;

    const int t = threadIdx.x;
    const int o_base = blockIdx.x * BO;
    const int n_base = blockIdx.y * BN;
    const int kz     = blockIdx.z;
    const int kc     = kz * KC;            // single K-chunk per CTA

    // thread grid 16(o) x 8(n); 4x4 micro-tile with +8 / +16 row splits
    const int tx = t & 15;                 // o quad: tx, tx+16, tx+32, tx+48
    const int ty = t >> 4;                 // n quad: ty, ty+8,  ty+16, ty+24

    // ---- stage tiles (coalesced LDG.128 -> STS.128) ----
    #pragma unroll
    for (int i = 0; i < BN * KC / 4 / NTHREADS; i++) {    // 8 iters
        int idx  = t + i * NTHREADS;
        int row  = idx >> 5;
        int col4 = idx & 31;
        *reinterpret_cast<float4*>(&xs[row][col4 * 4]) =
            *reinterpret_cast<const float4*>(&x[(n_base + row) * IN_TOT + kc + col4 * 4]);
    }
    #pragma unroll
    for (int i = 0; i < BO * KC / 4 / NTHREADS; i++) {    // 16 iters
        int idx  = t + i * NTHREADS;
        int row  = idx >> 5;
        int col4 = idx & 31;
        *reinterpret_cast<float4*>(&ws[row][col4 * 4]) =
            *reinterpret_cast<const float4*>(&w[(o_base + row) * IN_TOT + kc + col4 * 4]);
    }
    __syncthreads();

    // ---- mainloop: 8 LDS.128 feed 128 FADD+FMNMX per k4 ----
    float acc[4][4];
    #pragma unroll
    for (int i = 0; i < 4; i++)
        #pragma unroll
        for (int j = 0; j < 4; j++)
            acc[i][j] = -CUDART_INF_F;

    #pragma unroll 4
    for (int k4 = 0; k4 < KC / 4; k4++) {
        float4 xv[4], wv[4];
        #pragma unroll
        for (int i = 0; i < 4; i++)
            xv[i] = *reinterpret_cast<const float4*>(&xs[ty + i * 8][k4 * 4]);
        #pragma unroll
        for (int j = 0; j < 4; j++)
            wv[j] = *reinterpret_cast<const float4*>(&ws[tx + j * 16][k4 * 4]);

        #pragma unroll
        for (int i = 0; i < 4; i++) {
            #pragma unroll
            for (int j = 0; j < 4; j++) {
                acc[i][j] = fmaxf(acc[i][j], xv[i].x + wv[j].x);
                acc[i][j] = fmaxf(acc[i][j], xv[i].y + wv[j].y);
                acc[i][j] = fmaxf(acc[i][j], xv[i].z + wv[j].z);
                acc[i][j] = fmaxf(acc[i][j], xv[i].w + wv[j].w);
            }
        }
    }

    // ---- write split-K partial ----
    float* p = g_partial + kz * (N_TOT * OUT_TOT);
    #pragma unroll
    for (int i = 0; i < 4; i++) {
        #pragma unroll
        for (int j = 0; j < 4; j++) {
            p[(n_base + ty + i * 8) * OUT_TOT + o_base + tx + j * 16] = acc[i][j];
        }
    }

    // ---- last CTA per (n,o)-tile reduces across kz ----
    __threadfence();
    __syncthreads();
    const int tile = blockIdx.y * TILES_O + blockIdx.x;
    if (t == 0) {
        int old = atomicAdd(&g_ticket[tile], 1);
        s_last = (old == KSPLIT - 1);
    }
    __syncthreads();

    if (s_last) {
        __threadfence();   // acquire: partials from other CTAs are visible
        // tile = BN x BO = 2048 floats = 512 float4; 128 threads * 4 float4
        #pragma unroll
        for (int j = 0; j < 4; j++) {
            int f   = j * NTHREADS + t;          // float4 index in tile
            int ln  = f >> 4;                    // 16 float4 per 64-o row
            int lo4 = f & 15;
            int base = (n_base + ln) * OUT_TOT + o_base + lo4 * 4;

            float4 m = *reinterpret_cast<const float4*>(&g_partial[base]);
            #pragma unroll
            for (int z = 1; z < KSPLIT; z++) {
                float4 v = *reinterpret_cast<const float4*>(
                    &g_partial[z * (N_TOT * OUT_TOT) + base]);
                m.x = fmaxf(m.x, v.x);
                m.y = fmaxf(m.y, v.y);
                m.z = fmaxf(m.z, v.z);
                m.w = fmaxf(m.w, v.w);
            }
            float4 b = *reinterpret_cast<const float4*>(&bias[o_base + lo4 * 4]);
            m.x += b.x; m.y += b.y; m.z += b.z; m.w += b.w;
            *reinterpret_cast<float4*>(&out[base]) = m;
        }
        if (t == 0) g_ticket[tile] = 0;   // reset for next graph replay
    }
}

extern "C" void kernel_launch(void* const* d_in, const int* in_sizes, int n_in,
                              void* d_out, int out_size) {
    const float* x    = (const float*)d_in[0];   // [128, 1024]
    const float* w    = (const float*)d_in[1];   // [1024, 1024]
    const float* bias = (const float*)d_in[2];   // [1024]
    float* out        = (float*)d_out;           // [128, 1024]

    dim3 grid(TILES_O, TILES_N, KSPLIT);         // 16 x 4 x 8 = 512 CTAs
    tropical_kernel<<<grid, NTHREADS>>>(x, w, bias, out);
}